// round 7
// baseline (speedup 1.0000x reference)
#include <cuda_runtime.h>
#include <cuda_fp16.h>
#include <mma.h>
#include <math.h>
#include <cstdint>

using namespace nvcuda;

#define Bdim 32
#define Tdim 32
#define Sdim 64
#define Hdim 1024
#define Edim 512
#define Vdim 32000
#define G3   3072
#define KX   1536
#define MROWS (Tdim*Bdim)
#define NBLK  (Vdim/64)
#define KSPL  8          // split-K for GRU/out GEMMs

// ---------------------------------------------------------------------------
// Persistent device scratch
// ---------------------------------------------------------------------------
__device__ __align__(16) __half d_wih0H[G3*KX];
__device__ __align__(16) __half d_wih0L[G3*KX];
__device__ __align__(16) __half d_whh0H[G3*Hdim];
__device__ __align__(16) __half d_whh0L[G3*Hdim];
__device__ __align__(16) __half d_wih1H[G3*Hdim];
__device__ __align__(16) __half d_wih1L[G3*Hdim];
__device__ __align__(16) __half d_whh1H[G3*Hdim];
__device__ __align__(16) __half d_whh1L[G3*Hdim];
__device__ __align__(16) __half d_WaH [Hdim*Hdim];
__device__ __align__(16) __half d_WaL [Hdim*Hdim];
__device__ __align__(16) __half d_WoutH[Hdim*2*Hdim];
__device__ __align__(16) __half d_WoutL[Hdim*2*Hdim];
__device__ __align__(16) __half d_ctxH[Bdim*Sdim*Hdim];
__device__ __align__(16) __half d_ctxL[Bdim*Sdim*Hdim];
__device__ __align__(16) __half d_Wgen[(size_t)Vdim*Hdim];
__device__ float  d_Ck [Bdim*Sdim*Hdim];      // context @ Wa^T (fp32)
__device__ __align__(16) __half d_XH  [Tdim*Bdim*KX];
__device__ __align__(16) __half d_XL  [Tdim*Bdim*KX];
__device__ __align__(16) __half d_h0H [Bdim*Hdim];
__device__ __align__(16) __half d_h0L [Bdim*Hdim];
__device__ __align__(16) __half d_h1H [Bdim*Hdim];
__device__ __align__(16) __half d_h1L [Bdim*Hdim];
__device__ float  d_h0f[Bdim*Hdim];
__device__ float  d_h1f[Bdim*Hdim];
__device__ float  d_giP[KSPL*Bdim*G3];
__device__ float  d_ghP[KSPL*Bdim*G3];
__device__ float  d_oP [KSPL*Bdim*Hdim];
__device__ __align__(16) __half d_yH  [Bdim*2*Hdim];
__device__ __align__(16) __half d_yL  [Bdim*2*Hdim];
__device__ float  d_outf[Bdim*Hdim];
__device__ __align__(16) __half d_OutAll[MROWS*Hdim];
__device__ float  d_partM[MROWS*NBLK];
__device__ float  d_partS[MROWS*NBLK];
__device__ float  d_lse  [MROWS];

__device__ __forceinline__ void split_write(float v, __half* hi, __half* lo) {
    __half h = __float2half_rn(v);
    *hi = h;
    *lo = __float2half_rn(v - __half2float(h));
}

__device__ __forceinline__ void cp16(void* sdst, const void* gsrc) {
    unsigned int s = (unsigned int)__cvta_generic_to_shared(sdst);
    asm volatile("cp.async.cg.shared.global [%0], [%1], 16;\n" :: "r"(s), "l"(gsrc));
}
#define CP_COMMIT() asm volatile("cp.async.commit_group;\n" ::: "memory")
#define CP_WAIT(n)  asm volatile("cp.async.wait_group %0;\n" :: "n"(n) : "memory")

// ---------------------------------------------------------------------------
// ONE fused convert kernel: all split-fp16 weights + context + plain Wgen.
// Grid-stride over the concatenated element space.
// ---------------------------------------------------------------------------
#define N_WIH0 (G3*KX)
#define N_WHH  (G3*Hdim)
#define N_WA   (Hdim*Hdim)
#define N_WOUT (Hdim*2*Hdim)
#define N_CTX  (Bdim*Sdim*Hdim)
#define N_WGEN ((size_t)Vdim*Hdim)
__global__ void k_cvt(const float* __restrict__ wih0, const float* __restrict__ whh0,
                      const float* __restrict__ wih1, const float* __restrict__ whh1,
                      const float* __restrict__ Wa,   const float* __restrict__ Wout,
                      const float* __restrict__ ctx,  const float* __restrict__ Wgen) {
    const size_t o1 = N_WIH0;
    const size_t o2 = o1 + N_WHH;
    const size_t o3 = o2 + N_WHH;
    const size_t o4 = o3 + N_WHH;
    const size_t o5 = o4 + N_WA;
    const size_t o6 = o5 + N_WOUT;
    const size_t o7 = o6 + N_CTX;
    const size_t total = o7 + N_WGEN;
    size_t stride = (size_t)gridDim.x * blockDim.x;
    for (size_t i = (size_t)blockIdx.x*blockDim.x + threadIdx.x; i < total; i += stride) {
        if      (i < o1) { size_t j = i;       split_write(wih0[j], d_wih0H+j, d_wih0L+j); }
        else if (i < o2) { size_t j = i - o1;  split_write(whh0[j], d_whh0H+j, d_whh0L+j); }
        else if (i < o3) { size_t j = i - o2;  split_write(wih1[j], d_wih1H+j, d_wih1L+j); }
        else if (i < o4) { size_t j = i - o3;  split_write(whh1[j], d_whh1H+j, d_whh1L+j); }
        else if (i < o5) { size_t j = i - o4;  split_write(Wa[j],   d_WaH+j,   d_WaL+j);   }
        else if (i < o6) { size_t j = i - o5;  split_write(Wout[j], d_WoutH+j, d_WoutL+j); }
        else if (i < o7) { size_t j = i - o6;  split_write(ctx[j],  d_ctxH+j,  d_ctxL+j);  }
        else             { size_t j = i - o7;  d_Wgen[j] = __float2half_rn(Wgen[j]);       }
    }
}

__global__ void k_embed(const int* __restrict__ wids, const int* __restrict__ sids,
                        const float* __restrict__ wemb, const float* __restrict__ semb) {
    int t = blockIdx.x, b = blockIdx.y;
    int wid = wids[b*Tdim + t];
    int sid = sids[b*Tdim + t];
    size_t base = (size_t)(t*Bdim + b)*KX;
    const float* wr = wemb + (size_t)wid*Edim;
    const float* sr = semb + (size_t)sid*Edim;
    for (int e = threadIdx.x; e < Edim; e += blockDim.x)
        split_write(wr[e] + sr[e], d_XH + base + e, d_XL + base + e);
}

__global__ void k_init(const float* __restrict__ hidden, const float* __restrict__ pout) {
    int i = blockIdx.x*blockDim.x + threadIdx.x;
    if (i >= Bdim*Hdim) return;
    int b = i / Hdim, j = i % Hdim;
    float h0 = hidden[i];
    float h1 = hidden[Bdim*Hdim + i];
    d_h0f[i] = h0;  d_h1f[i] = h1;
    split_write(h0, d_h0H + i, d_h0L + i);
    split_write(h1, d_h1H + i, d_h1L + i);
    size_t xo = (size_t)b*KX + Edim + j;
    split_write(pout[i], d_XH + xo, d_XL + xo);
}

// ---------------------------------------------------------------------------
// Ck = context @ Wa^T : [2048,1024] x [1024,1024], split-fp16, one-time.
// grid (16, 64), 128 threads (4 warps; each warp 16-wide n, 2 m-tiles).
// ---------------------------------------------------------------------------
__global__ void k_ck() {
    int warp = threadIdx.x >> 5;
    int n0 = blockIdx.x*64 + warp*16;
    int m0 = blockIdx.y*32;
    const int K = Hdim;
    const __half* AH = d_ctxH + (size_t)m0*K;
    const __half* AL = d_ctxL + (size_t)m0*K;
    wmma::fragment<wmma::matrix_a,16,16,16,__half,wmma::row_major> aH[2], aL[2];
    wmma::fragment<wmma::matrix_b,16,16,16,__half,wmma::col_major> bH, bL;
    wmma::fragment<wmma::accumulator,16,16,16,float> c[2];
    wmma::fill_fragment(c[0], 0.f);
    wmma::fill_fragment(c[1], 0.f);
    #pragma unroll 2
    for (int k = 0; k < K; k += 16) {
        wmma::load_matrix_sync(bH, d_WaH + (size_t)n0*K + k, K);
        wmma::load_matrix_sync(bL, d_WaL + (size_t)n0*K + k, K);
        #pragma unroll
        for (int i = 0; i < 2; i++) {
            wmma::load_matrix_sync(aH[i], AH + (size_t)(i*16)*K + k, K);
            wmma::load_matrix_sync(aL[i], AL + (size_t)(i*16)*K + k, K);
        }
        #pragma unroll
        for (int i = 0; i < 2; i++) {
            wmma::mma_sync(c[i], aH[i], bH, c[i]);
            wmma::mma_sync(c[i], aH[i], bL, c[i]);
            wmma::mma_sync(c[i], aL[i], bH, c[i]);
        }
    }
    #pragma unroll
    for (int i = 0; i < 2; i++)
        wmma::store_matrix_sync(d_Ck + (size_t)(m0 + i*16)*Hdim + n0, c[i],
                                Hdim, wmma::mem_row_major);
}
// NOTE: Ck[r,h] = sum_j ctx[r,j]*Wa[h,j]  (col-major B over Wa rows) — matches
// scores[b,s] = sum_h h1[h] * Ck[b*S+s, h].

// ---------------------------------------------------------------------------
// Dual split-fp16 GRU GEMM, split-K via gridDim.y. grid (48, KSPL, 2), 128 thr.
// ---------------------------------------------------------------------------
__global__ void k_gru_gemm(const __half* __restrict__ XaH, const __half* __restrict__ XaL, int Ka,
                           const __half* __restrict__ WaH_, const __half* __restrict__ WaL_,
                           float* __restrict__ Ya,
                           const __half* __restrict__ XbH, const __half* __restrict__ XbL, int Kb,
                           const __half* __restrict__ WbH_, const __half* __restrict__ WbL_,
                           float* __restrict__ Yb, int N) {
    const __half *XH, *XL, *WH, *WL; float* Y; int K;
    if (blockIdx.z == 0) { XH = XaH; XL = XaL; WH = WaH_; WL = WaL_; Y = Ya; K = Ka; }
    else                 { XH = XbH; XL = XbL; WH = WbH_; WL = WbL_; Y = Yb; K = Kb; }
    int warp = threadIdx.x >> 5;
    int n0 = blockIdx.x*64 + warp*16;
    int kchunk = K / gridDim.y;
    int k0 = blockIdx.y * kchunk;
    wmma::fragment<wmma::matrix_a, 16,16,16, __half, wmma::row_major> aH[2], aL[2];
    wmma::fragment<wmma::matrix_b, 16,16,16, __half, wmma::col_major> bH, bL;
    wmma::fragment<wmma::accumulator, 16,16,16, float> c[2];
    wmma::fill_fragment(c[0], 0.f);
    wmma::fill_fragment(c[1], 0.f);
    #pragma unroll 2
    for (int k = k0; k < k0 + kchunk; k += 16) {
        wmma::load_matrix_sync(bH, WH + (size_t)n0*K + k, K);
        wmma::load_matrix_sync(bL, WL + (size_t)n0*K + k, K);
        #pragma unroll
        for (int i = 0; i < 2; i++) {
            wmma::load_matrix_sync(aH[i], XH + (size_t)(i*16)*K + k, K);
            wmma::load_matrix_sync(aL[i], XL + (size_t)(i*16)*K + k, K);
        }
        #pragma unroll
        for (int i = 0; i < 2; i++) {
            wmma::mma_sync(c[i], aH[i], bH, c[i]);
            wmma::mma_sync(c[i], aH[i], bL, c[i]);
            wmma::mma_sync(c[i], aL[i], bH, c[i]);
        }
    }
    float* Yp = Y + (size_t)blockIdx.y * Bdim * N;
    #pragma unroll
    for (int i = 0; i < 2; i++)
        wmma::store_matrix_sync(Yp + (size_t)(i*16)*N + n0, c[i], N, wmma::mem_row_major);
}

// ---------------------------------------------------------------------------
// GRU gate math; sums KSPL split-K partials; biases folded.
// ---------------------------------------------------------------------------
__global__ void k_gate(const float* __restrict__ giP, const float* __restrict__ ghP,
                       const float* __restrict__ bih, const float* __restrict__ bhh,
                       float* __restrict__ hf, __half* __restrict__ hH, __half* __restrict__ hL,
                       int writeY) {
    int i = blockIdx.x*blockDim.x + threadIdx.x;
    if (i >= Bdim*Hdim) return;
    int b = i / Hdim, j = i % Hdim;
    size_t o0 = (size_t)b*G3 + j;
    const size_t PS = (size_t)Bdim*G3;
    float gr = 0.f, gz = 0.f, gn = 0.f, hr = 0.f, hz = 0.f, hn = 0.f;
    #pragma unroll
    for (int s = 0; s < KSPL; s++) {
        gr += giP[s*PS + o0];
        gz += giP[s*PS + o0 + Hdim];
        gn += giP[s*PS + o0 + 2*Hdim];
        hr += ghP[s*PS + o0];
        hz += ghP[s*PS + o0 + Hdim];
        hn += ghP[s*PS + o0 + 2*Hdim];
    }
    float r = 1.f/(1.f + expf(-(gr + bih[j]        + hr + bhh[j])));
    float z = 1.f/(1.f + expf(-(gz + bih[Hdim+j]   + hz + bhh[Hdim+j])));
    float n = tanhf(gn + bih[2*Hdim+j] + r*(hn + bhh[2*Hdim+j]));
    float h = (1.f - z)*n + z*hf[i];
    hf[i] = h;
    split_write(h, hH + i, hL + i);
    if (writeY) {
        size_t yo = (size_t)b*2*Hdim + Hdim + j;
        split_write(h, d_yH + yo, d_yL + yo);
    }
}

// ---------------------------------------------------------------------------
// Attention per batch row; scores from fp32 h1 · Ck (q-GEMM eliminated).
// grid (32), 256 threads.
// ---------------------------------------------------------------------------
__global__ void k_attn(const float* __restrict__ context) {
    int b = blockIdx.x;
    int tid = threadIdx.x;
    __shared__ float qs[Hdim];
    __shared__ float sc[Sdim];
    for (int j = tid; j < Hdim; j += 256) qs[j] = d_h1f[(size_t)b*Hdim + j];
    __syncthreads();
    int warp = tid >> 5, lane = tid & 31;
    for (int s = warp; s < Sdim; s += 8) {
        const float* cr = d_Ck + (size_t)(b*Sdim + s)*Hdim;
        float sum = 0.f;
        for (int j = lane; j < Hdim; j += 32) sum += qs[j]*cr[j];
        #pragma unroll
        for (int o = 16; o; o >>= 1) sum += __shfl_xor_sync(0xffffffffu, sum, o);
        if (!lane) sc[s] = sum;
    }
    __syncthreads();
    float m = -1e30f;
    for (int s = 0; s < Sdim; s++) m = fmaxf(m, sc[s]);
    float ssum = 0.f;
    for (int s = 0; s < Sdim; s++) ssum += expf(sc[s] - m);
    __syncthreads();
    if (tid < Sdim) sc[tid] = expf(sc[tid] - m) / ssum;
    __syncthreads();
    const float* cb = context + (size_t)b*Sdim*Hdim;
    for (int j = tid; j < Hdim; j += 256) {
        float acc = 0.f;
        #pragma unroll 8
        for (int s = 0; s < Sdim; s++) acc += sc[s]*cb[(size_t)s*Hdim + j];
        size_t yo = (size_t)b*2*Hdim + j;
        split_write(acc, d_yH + yo, d_yL + yo);
    }
}

// ---------------------------------------------------------------------------
// out partials = [c;h1] @ W_out^T (split). grid (16, KSPL), 128 threads.
// ---------------------------------------------------------------------------
__global__ void k_out() {
    int warp = threadIdx.x >> 5;
    int n0 = blockIdx.x*64 + warp*16;
    const int K = 2*Hdim;
    int kchunk = K / gridDim.y;
    int k0 = blockIdx.y * kchunk;
    wmma::fragment<wmma::matrix_a, 16,16,16, __half, wmma::row_major> aH[2], aL[2];
    wmma::fragment<wmma::matrix_b, 16,16,16, __half, wmma::col_major> bH, bL;
    wmma::fragment<wmma::accumulator, 16,16,16, float> c[2];
    wmma::fill_fragment(c[0], 0.f);
    wmma::fill_fragment(c[1], 0.f);
    #pragma unroll 2
    for (int k = k0; k < k0 + kchunk; k += 16) {
        wmma::load_matrix_sync(bH, d_WoutH + (size_t)n0*K + k, K);
        wmma::load_matrix_sync(bL, d_WoutL + (size_t)n0*K + k, K);
        #pragma unroll
        for (int i = 0; i < 2; i++) {
            wmma::load_matrix_sync(aH[i], d_yH + (size_t)(i*16)*K + k, K);
            wmma::load_matrix_sync(aL[i], d_yL + (size_t)(i*16)*K + k, K);
        }
        #pragma unroll
        for (int i = 0; i < 2; i++) {
            wmma::mma_sync(c[i], aH[i], bH, c[i]);
            wmma::mma_sync(c[i], aH[i], bL, c[i]);
            wmma::mma_sync(c[i], aL[i], bH, c[i]);
        }
    }
    float* Yp = d_oP + (size_t)blockIdx.y * Bdim * Hdim;
    #pragma unroll
    for (int i = 0; i < 2; i++)
        wmma::store_matrix_sync(Yp + (size_t)(i*16)*Hdim + n0, c[i], Hdim, wmma::mem_row_major);
}

// ---------------------------------------------------------------------------
// Finish out: tanh(sum KSPL partials); scatter to OutAll + next input feed.
// ---------------------------------------------------------------------------
__global__ void k_outfin(int t) {
    int i = blockIdx.x*blockDim.x + threadIdx.x;
    if (i >= Bdim*Hdim) return;
    int b = i / Hdim, j = i % Hdim;
    const size_t PS = (size_t)Bdim*Hdim;
    float acc = 0.f;
    #pragma unroll
    for (int s = 0; s < KSPL; s++) acc += d_oP[s*PS + i];
    float v = tanhf(acc);
    d_outf[i] = v;
    d_OutAll[(size_t)t*Bdim*Hdim + i] = __float2half_rn(v);
    if (t + 1 < Tdim) {
        size_t xo = (size_t)((t+1)*Bdim + b)*KX + Edim + j;
        split_write(v, d_XH + xo, d_XL + xo);
    }
}

// ---------------------------------------------------------------------------
// Generator GEMM with cp.async 2-stage pipeline. BM=128, BN=64, BK=32.
// grid (500, 8), 256 threads.
// ---------------------------------------------------------------------------
#define GLDA 40
__global__ void k_gen(const float* __restrict__ bgen, float* __restrict__ logits) {
    __shared__ __align__(16) __half As[2][128*GLDA];
    __shared__ __align__(16) __half Bs[2][64*GLDA];
    __shared__ float Cs[64*68];
    int nb = blockIdx.x, mb = blockIdx.y;
    int n0 = nb*64, m0 = mb*128;
    int tid = threadIdx.x, warp = tid >> 5;
    int wm = warp >> 1, wn = warp & 1;
    const int K = Hdim;
    wmma::fragment<wmma::accumulator, 16,16,16, float> c[2][2];
    #pragma unroll
    for (int i = 0; i < 2; i++)
        #pragma unroll
        for (int j = 0; j < 2; j++)
            wmma::fill_fragment(c[i][j], 0.f);

    auto loadStage = [&](int stage, int kt) {
        int k0 = kt*32;
        #pragma unroll
        for (int rep = 0; rep < 2; rep++) {
            int ch = tid + rep*256;
            int row = ch >> 2, part = ch & 3;
            cp16(&As[stage][row*GLDA + part*8],
                 &d_OutAll[(size_t)(m0+row)*K + k0 + part*8]);
        }
        {
            int row = tid >> 2, part = tid & 3;
            cp16(&Bs[stage][row*GLDA + part*8],
                 &d_Wgen[(size_t)(n0+row)*K + k0 + part*8]);
        }
    };

    loadStage(0, 0);
    CP_COMMIT();
    const int nIter = K/32;
    for (int kt = 0; kt < nIter; ++kt) {
        int cur = kt & 1;
        if (kt + 1 < nIter) {
            loadStage(cur ^ 1, kt + 1);
            CP_COMMIT();
            CP_WAIT(1);
        } else {
            CP_WAIT(0);
        }
        __syncthreads();
        #pragma unroll
        for (int s = 0; s < 32; s += 16) {
            wmma::fragment<wmma::matrix_a, 16,16,16, __half, wmma::row_major> a[2];
            wmma::fragment<wmma::matrix_b, 16,16,16, __half, wmma::col_major> bfr[2];
            #pragma unroll
            for (int i = 0; i < 2; i++)
                wmma::load_matrix_sync(a[i], &As[cur][(wm*32 + i*16)*GLDA + s], GLDA);
            #pragma unroll
            for (int j = 0; j < 2; j++)
                wmma::load_matrix_sync(bfr[j], &Bs[cur][(wn*32 + j*16)*GLDA + s], GLDA);
            #pragma unroll
            for (int i = 0; i < 2; i++)
                #pragma unroll
                for (int j = 0; j < 2; j++)
                    wmma::mma_sync(c[i][j], a[i], bfr[j], c[i][j]);
        }
        __syncthreads();
    }

    for (int hid = 0; hid < 2; ++hid) {
        if ((wm >> 1) == hid) {
            int wmL = wm & 1;
            #pragma unroll
            for (int i = 0; i < 2; i++)
                #pragma unroll
                for (int j = 0; j < 2; j++)
                    wmma::store_matrix_sync(&Cs[(wmL*32 + i*16)*68 + wn*32 + j*16],
                                            c[i][j], 68, wmma::mem_row_major);
        }
        __syncthreads();
        if (tid < 64) {
            int r = m0 + hid*64 + tid;
            float mx = -1e30f;
            for (int cc = 0; cc < 64; ++cc)
                mx = fmaxf(mx, Cs[tid*68 + cc] + bgen[n0 + cc]);
            float sm = 0.f;
            for (int cc = 0; cc < 64; ++cc)
                sm += expf(Cs[tid*68 + cc] + bgen[n0 + cc] - mx);
            d_partM[(size_t)r*NBLK + nb] = mx;
            d_partS[(size_t)r*NBLK + nb] = sm;
        }
        for (int e = tid; e < 64*64; e += 256) {
            int i = e >> 6, cc = e & 63;
            int r = m0 + hid*64 + i;
            logits[(size_t)r*Vdim + n0 + cc] = Cs[i*68 + cc] + bgen[n0 + cc];
        }
        __syncthreads();
    }
}

// ---------------------------------------------------------------------------
__global__ void k_combine() {
    int r = blockIdx.x, tid = threadIdx.x;
    float m = -1e30f, s = 0.f;
    for (int i = tid; i < NBLK; i += blockDim.x) {
        float mi = d_partM[(size_t)r*NBLK + i];
        float si = d_partS[(size_t)r*NBLK + i];
        float M = fmaxf(m, mi);
        s = s*expf(m - M) + si*expf(mi - M);
        m = M;
    }
    __shared__ float sm[128], ss[128];
    sm[tid] = m; ss[tid] = s;
    __syncthreads();
    for (int o = 64; o; o >>= 1) {
        if (tid < o) {
            float M = fmaxf(sm[tid], sm[tid+o]);
            ss[tid] = ss[tid]*expf(sm[tid] - M) + ss[tid+o]*expf(sm[tid+o] - M);
            sm[tid] = M;
        }
        __syncthreads();
    }
    if (!tid) d_lse[r] = sm[0] + logf(ss[0]);
}

__global__ void k_norm(float* __restrict__ logits) {
    int r = blockIdx.y;
    int i = blockIdx.x*blockDim.x + threadIdx.x;
    if (i < Vdim/4) {
        float4* p = (float4*)(logits + (size_t)r*Vdim);
        float l = d_lse[r];
        float4 v = p[i];
        v.x -= l; v.y -= l; v.z -= l; v.w -= l;
        p[i] = v;
    }
}

__global__ void k_final(float* __restrict__ tail) {
    int i = blockIdx.x*blockDim.x + threadIdx.x;
    const int BH = Bdim*Hdim;
    if (i < BH) {
        tail[i]        = d_h0f[i];
        tail[BH + i]   = d_h1f[i];
        tail[2*BH + i] = d_outf[i];
    }
}

// ---------------------------------------------------------------------------
extern "C" void kernel_launch(void* const* d_in, const int* in_sizes, int n_in,
                              void* d_out, int out_size) {
    (void)in_sizes; (void)n_in; (void)out_size;
    const int*   word_ids = (const int*)  d_in[0];
    const int*   spec_ids = (const int*)  d_in[1];
    const float* word_emb = (const float*)d_in[3];
    const float* spec_emb = (const float*)d_in[4];
    const float* wih0     = (const float*)d_in[5];
    const float* whh0     = (const float*)d_in[6];
    const float* bih0     = (const float*)d_in[7];
    const float* bhh0     = (const float*)d_in[8];
    const float* wih1     = (const float*)d_in[9];
    const float* whh1     = (const float*)d_in[10];
    const float* bih1     = (const float*)d_in[11];
    const float* bhh1     = (const float*)d_in[12];
    const float* Wa       = (const float*)d_in[13];
    const float* Wout     = (const float*)d_in[14];
    const float* Wgen     = (const float*)d_in[15];
    const float* bgen     = (const float*)d_in[16];
    const float* hidden   = (const float*)d_in[17];
    const float* pout     = (const float*)d_in[18];
    const float* context  = (const float*)d_in[19];
    float* outp = (float*)d_out;

    #define SYM(sym, ty, name) ty* name; { void* _p; cudaGetSymbolAddress(&_p, sym); name = (ty*)_p; }
    SYM(d_wih0H, __half, pwih0H)  SYM(d_wih0L, __half, pwih0L)
    SYM(d_whh0H, __half, pwhh0H)  SYM(d_whh0L, __half, pwhh0L)
    SYM(d_wih1H, __half, pwih1H)  SYM(d_wih1L, __half, pwih1L)
    SYM(d_whh1H, __half, pwhh1H)  SYM(d_whh1L, __half, pwhh1L)
    SYM(d_XH,    __half, pXH)     SYM(d_XL,    __half, pXL)
    SYM(d_h0H,   __half, ph0H)    SYM(d_h0L,   __half, ph0L)
    SYM(d_h1H,   __half, ph1H)    SYM(d_h1L,   __half, ph1L)
    SYM(d_h0f,   float,  ph0f)    SYM(d_h1f,   float,  ph1f)
    SYM(d_giP,   float,  pgiP)    SYM(d_ghP,   float,  pghP)
    #undef SYM

    k_cvt<<<4096, 256>>>(wih0, whh0, wih1, whh1, Wa, Wout, context, Wgen);
    k_embed<<<dim3(Tdim, Bdim), 256>>>(word_ids, spec_ids, word_emb, spec_emb);
    k_init<<<(Bdim*Hdim + 255)/256, 256>>>(hidden, pout);
    k_ck<<<dim3(16, 64), 128>>>();

    const int BH = Bdim*Hdim;
    for (int t = 0; t < Tdim; ++t) {
        const __half* XtH = pXH + (size_t)t*Bdim*KX;
        const __half* XtL = pXL + (size_t)t*Bdim*KX;
        k_gru_gemm<<<dim3(48,KSPL,2), 128>>>(XtH, XtL, KX, pwih0H, pwih0L, pgiP,
                                             ph0H, ph0L, Hdim, pwhh0H, pwhh0L, pghP, G3);
        k_gate<<<(BH + 255)/256, 256>>>(pgiP, pghP, bih0, bhh0, ph0f, ph0H, ph0L, 0);
        k_gru_gemm<<<dim3(48,KSPL,2), 128>>>(ph0H, ph0L, Hdim, pwih1H, pwih1L, pgiP,
                                             ph1H, ph1L, Hdim, pwhh1H, pwhh1L, pghP, G3);
        k_gate<<<(BH + 255)/256, 256>>>(pgiP, pghP, bih1, bhh1, ph1f, ph1H, ph1L, 1);
        k_attn<<<Bdim, 256>>>(context);
        k_out<<<dim3(16,KSPL), 128>>>();
        k_outfin<<<(BH + 255)/256, 256>>>(t);
    }

    k_gen<<<dim3(NBLK, MROWS/128), 256>>>(bgen, outp);
    k_combine<<<MROWS, 128>>>();
    k_norm<<<dim3(32, MROWS), 256>>>(outp);
    k_final<<<(BH + 255)/256, 256>>>(outp + (size_t)MROWS*Vdim);
}

// round 8
// speedup vs baseline: 1.9758x; 1.9758x over previous
#include <cuda_runtime.h>
#include <cuda_fp16.h>
#include <mma.h>
#include <math.h>
#include <cstdint>

using namespace nvcuda;

#define Bdim 32
#define Tdim 32
#define Sdim 64
#define Hdim 1024
#define Edim 512
#define Vdim 32000
#define G3   3072
#define KX   1536
#define MROWS (Tdim*Bdim)
#define NBLK  (Vdim/64)
#define KSPL  4
#define BK    32
#define SLDA  40      // BK + 8 pad (halves)

// ---------------------------------------------------------------------------
__device__ __align__(16) __half d_wih0H[G3*KX];
__device__ __align__(16) __half d_wih0L[G3*KX];
__device__ __align__(16) __half d_whh0H[G3*Hdim];
__device__ __align__(16) __half d_whh0L[G3*Hdim];
__device__ __align__(16) __half d_wih1H[G3*Hdim];
__device__ __align__(16) __half d_wih1L[G3*Hdim];
__device__ __align__(16) __half d_whh1H[G3*Hdim];
__device__ __align__(16) __half d_whh1L[G3*Hdim];
__device__ __align__(16) __half d_WaH [Hdim*Hdim];
__device__ __align__(16) __half d_WaL [Hdim*Hdim];
__device__ __align__(16) __half d_WoutH[Hdim*2*Hdim];
__device__ __align__(16) __half d_WoutL[Hdim*2*Hdim];
__device__ __align__(16) __half d_ctxH[Bdim*Sdim*Hdim];
__device__ __align__(16) __half d_ctxL[Bdim*Sdim*Hdim];
__device__ __align__(16) __half d_Wgen[(size_t)Vdim*Hdim];
__device__ float  d_Ck [Bdim*Sdim*Hdim];
__device__ __align__(16) __half d_XH  [Tdim*Bdim*KX];
__device__ __align__(16) __half d_XL  [Tdim*Bdim*KX];
__device__ __align__(16) __half d_h0H [Bdim*Hdim];
__device__ __align__(16) __half d_h0L [Bdim*Hdim];
__device__ __align__(16) __half d_h1H [Bdim*Hdim];
__device__ __align__(16) __half d_h1L [Bdim*Hdim];
__device__ float  d_h0f[Bdim*Hdim];
__device__ float  d_h1f[Bdim*Hdim];
__device__ float  d_giP[KSPL*Bdim*G3];
__device__ float  d_ghP[KSPL*Bdim*G3];
__device__ float  d_oP [KSPL*Bdim*Hdim];
__device__ __align__(16) __half d_yH  [Bdim*2*Hdim];
__device__ __align__(16) __half d_yL  [Bdim*2*Hdim];
__device__ float  d_outf[Bdim*Hdim];
__device__ __align__(16) __half d_OutAll[MROWS*Hdim];
__device__ float  d_partM[MROWS*NBLK];
__device__ float  d_partS[MROWS*NBLK];
__device__ float  d_lse  [MROWS];

__device__ __forceinline__ void split_write(float v, __half* hi, __half* lo) {
    __half h = __float2half_rn(v);
    *hi = h;
    *lo = __float2half_rn(v - __half2float(h));
}

__device__ __forceinline__ void cp16(void* sdst, const void* gsrc) {
    unsigned int s = (unsigned int)__cvta_generic_to_shared(sdst);
    asm volatile("cp.async.cg.shared.global [%0], [%1], 16;\n" :: "r"(s), "l"(gsrc));
}
#define CP_COMMIT() asm volatile("cp.async.commit_group;\n" ::: "memory")
#define CP_WAIT(n)  asm volatile("cp.async.wait_group %0;\n" :: "n"(n) : "memory")

// ---------------------------------------------------------------------------
// Fused convert: all split-fp16 weights + context + plain Wgen.
// ---------------------------------------------------------------------------
#define N_WIH0 (G3*KX)
#define N_WHH  (G3*Hdim)
#define N_WA   (Hdim*Hdim)
#define N_WOUT (Hdim*2*Hdim)
#define N_CTX  (Bdim*Sdim*Hdim)
#define N_WGEN ((size_t)Vdim*Hdim)
__global__ void k_cvt(const float* __restrict__ wih0, const float* __restrict__ whh0,
                      const float* __restrict__ wih1, const float* __restrict__ whh1,
                      const float* __restrict__ Wa,   const float* __restrict__ Wout,
                      const float* __restrict__ ctx,  const float* __restrict__ Wgen) {
    const size_t o1 = N_WIH0;
    const size_t o2 = o1 + N_WHH;
    const size_t o3 = o2 + N_WHH;
    const size_t o4 = o3 + N_WHH;
    const size_t o5 = o4 + N_WA;
    const size_t o6 = o5 + N_WOUT;
    const size_t o7 = o6 + N_CTX;
    const size_t total = o7 + N_WGEN;
    size_t stride = (size_t)gridDim.x * blockDim.x;
    for (size_t i = (size_t)blockIdx.x*blockDim.x + threadIdx.x; i < total; i += stride) {
        if      (i < o1) { size_t j = i;       split_write(wih0[j], d_wih0H+j, d_wih0L+j); }
        else if (i < o2) { size_t j = i - o1;  split_write(whh0[j], d_whh0H+j, d_whh0L+j); }
        else if (i < o3) { size_t j = i - o2;  split_write(wih1[j], d_wih1H+j, d_wih1L+j); }
        else if (i < o4) { size_t j = i - o3;  split_write(whh1[j], d_whh1H+j, d_whh1L+j); }
        else if (i < o5) { size_t j = i - o4;  split_write(Wa[j],   d_WaH+j,   d_WaL+j);   }
        else if (i < o6) { size_t j = i - o5;  split_write(Wout[j], d_WoutH+j, d_WoutL+j); }
        else if (i < o7) { size_t j = i - o6;  split_write(ctx[j],  d_ctxH+j,  d_ctxL+j);  }
        else             { size_t j = i - o7;  d_Wgen[j] = __float2half_rn(Wgen[j]);       }
    }
}

__global__ void k_embed(const int* __restrict__ wids, const int* __restrict__ sids,
                        const float* __restrict__ wemb, const float* __restrict__ semb) {
    int t = blockIdx.x, b = blockIdx.y;
    int wid = wids[b*Tdim + t];
    int sid = sids[b*Tdim + t];
    size_t base = (size_t)(t*Bdim + b)*KX;
    const float* wr = wemb + (size_t)wid*Edim;
    const float* sr = semb + (size_t)sid*Edim;
    for (int e = threadIdx.x; e < Edim; e += blockDim.x)
        split_write(wr[e] + sr[e], d_XH + base + e, d_XL + base + e);
}

__global__ void k_init(const float* __restrict__ hidden, const float* __restrict__ pout) {
    int i = blockIdx.x*blockDim.x + threadIdx.x;
    if (i >= Bdim*Hdim) return;
    int b = i / Hdim, j = i % Hdim;
    float h0 = hidden[i];
    float h1 = hidden[Bdim*Hdim + i];
    d_h0f[i] = h0;  d_h1f[i] = h1;
    split_write(h0, d_h0H + i, d_h0L + i);
    split_write(h1, d_h1H + i, d_h1L + i);
    size_t xo = (size_t)b*KX + Edim + j;
    split_write(pout[i], d_XH + xo, d_XL + xo);
}

// ---------------------------------------------------------------------------
// Ck = context @ Wa^T, pipelined smem GEMM. BM=64, BN=64, BK=32.
// grid (16, 32), 128 threads.
// ---------------------------------------------------------------------------
__global__ void k_ck() {
    __shared__ __align__(16) __half AsH[2][64*SLDA], AsL[2][64*SLDA];
    __shared__ __align__(16) __half BsH[2][64*SLDA], BsL[2][64*SLDA];
    int tid = threadIdx.x, warp = tid >> 5;
    int n0 = blockIdx.x*64, m0 = blockIdx.y*64;
    const int K = Hdim;
    wmma::fragment<wmma::accumulator,16,16,16,float> c[4];
    #pragma unroll
    for (int i = 0; i < 4; i++) wmma::fill_fragment(c[i], 0.f);

    auto load = [&](int st, int k0) {
        #pragma unroll
        for (int rep = 0; rep < 2; rep++) {
            int ch = tid + rep*128;
            int r = ch >> 2, p = ch & 3;
            cp16(&AsH[st][r*SLDA + p*8], d_ctxH + (size_t)(m0+r)*K + k0 + p*8);
            cp16(&AsL[st][r*SLDA + p*8], d_ctxL + (size_t)(m0+r)*K + k0 + p*8);
            cp16(&BsH[st][r*SLDA + p*8], d_WaH  + (size_t)(n0+r)*K + k0 + p*8);
            cp16(&BsL[st][r*SLDA + p*8], d_WaL  + (size_t)(n0+r)*K + k0 + p*8);
        }
    };
    load(0, 0);
    CP_COMMIT();
    const int nIter = K/BK;
    for (int it = 0; it < nIter; ++it) {
        int cur = it & 1;
        if (it + 1 < nIter) { load(cur^1, (it+1)*BK); CP_COMMIT(); CP_WAIT(1); }
        else CP_WAIT(0);
        __syncthreads();
        #pragma unroll
        for (int ks = 0; ks < 2; ks++) {
            wmma::fragment<wmma::matrix_b,16,16,16,__half,wmma::col_major> bH, bL;
            wmma::load_matrix_sync(bH, &BsH[cur][(warp*16)*SLDA + ks*16], SLDA);
            wmma::load_matrix_sync(bL, &BsL[cur][(warp*16)*SLDA + ks*16], SLDA);
            #pragma unroll
            for (int m = 0; m < 4; m++) {
                wmma::fragment<wmma::matrix_a,16,16,16,__half,wmma::row_major> aH, aL;
                wmma::load_matrix_sync(aH, &AsH[cur][(m*16)*SLDA + ks*16], SLDA);
                wmma::load_matrix_sync(aL, &AsL[cur][(m*16)*SLDA + ks*16], SLDA);
                wmma::mma_sync(c[m], aH, bH, c[m]);
                wmma::mma_sync(c[m], aH, bL, c[m]);
                wmma::mma_sync(c[m], aL, bH, c[m]);
            }
        }
        __syncthreads();
    }
    #pragma unroll
    for (int m = 0; m < 4; m++)
        wmma::store_matrix_sync(d_Ck + (size_t)(m0 + m*16)*Hdim + n0 + warp*16,
                                c[m], Hdim, wmma::mem_row_major);
}

// ---------------------------------------------------------------------------
// Dual GRU GEMM, smem-staged + cp.async pipeline, split-K via gridDim.y.
// grid (48, KSPL, 2), 128 threads. M=32, BN=64, BK=32.
// ---------------------------------------------------------------------------
__global__ void k_gru_gemm(const __half* __restrict__ XaH, const __half* __restrict__ XaL, int Ka,
                           const __half* __restrict__ WaH_, const __half* __restrict__ WaL_,
                           float* __restrict__ Ya,
                           const __half* __restrict__ XbH, const __half* __restrict__ XbL, int Kb,
                           const __half* __restrict__ WbH_, const __half* __restrict__ WbL_,
                           float* __restrict__ Yb, int N) {
    const __half *XH, *XL, *WH, *WL; float* Y; int K;
    if (blockIdx.z == 0) { XH = XaH; XL = XaL; WH = WaH_; WL = WaL_; Y = Ya; K = Ka; }
    else                 { XH = XbH; XL = XbL; WH = WbH_; WL = WbL_; Y = Yb; K = Kb; }
    __shared__ __align__(16) __half AsH[2][32*SLDA], AsL[2][32*SLDA];
    __shared__ __align__(16) __half BsH[2][64*SLDA], BsL[2][64*SLDA];
    int tid = threadIdx.x, warp = tid >> 5;
    int n0 = blockIdx.x*64;
    int kchunk = K / gridDim.y;
    int kbase = blockIdx.y * kchunk;

    wmma::fragment<wmma::accumulator,16,16,16,float> c[2];
    wmma::fill_fragment(c[0], 0.f);
    wmma::fill_fragment(c[1], 0.f);

    auto load = [&](int st, int k0) {
        {
            int r = tid >> 2, p = tid & 3;     // A: 32 rows × 64B
            cp16(&AsH[st][r*SLDA + p*8], XH + (size_t)r*K + k0 + p*8);
            cp16(&AsL[st][r*SLDA + p*8], XL + (size_t)r*K + k0 + p*8);
        }
        #pragma unroll
        for (int rep = 0; rep < 2; rep++) {    // B: 64 rows × 64B
            int ch = tid + rep*128;
            int r = ch >> 2, p = ch & 3;
            cp16(&BsH[st][r*SLDA + p*8], WH + (size_t)(n0+r)*K + k0 + p*8);
            cp16(&BsL[st][r*SLDA + p*8], WL + (size_t)(n0+r)*K + k0 + p*8);
        }
    };
    load(0, kbase);
    CP_COMMIT();
    const int nIter = kchunk/BK;
    for (int it = 0; it < nIter; ++it) {
        int cur = it & 1;
        if (it + 1 < nIter) { load(cur^1, kbase + (it+1)*BK); CP_COMMIT(); CP_WAIT(1); }
        else CP_WAIT(0);
        __syncthreads();
        #pragma unroll
        for (int ks = 0; ks < 2; ks++) {
            wmma::fragment<wmma::matrix_b,16,16,16,__half,wmma::col_major> bH, bL;
            wmma::load_matrix_sync(bH, &BsH[cur][(warp*16)*SLDA + ks*16], SLDA);
            wmma::load_matrix_sync(bL, &BsL[cur][(warp*16)*SLDA + ks*16], SLDA);
            #pragma unroll
            for (int m = 0; m < 2; m++) {
                wmma::fragment<wmma::matrix_a,16,16,16,__half,wmma::row_major> aH, aL;
                wmma::load_matrix_sync(aH, &AsH[cur][(m*16)*SLDA + ks*16], SLDA);
                wmma::load_matrix_sync(aL, &AsL[cur][(m*16)*SLDA + ks*16], SLDA);
                wmma::mma_sync(c[m], aH, bH, c[m]);
                wmma::mma_sync(c[m], aH, bL, c[m]);
                wmma::mma_sync(c[m], aL, bH, c[m]);
            }
        }
        __syncthreads();
    }
    float* Yp = Y + (size_t)blockIdx.y * Bdim * N;
    #pragma unroll
    for (int m = 0; m < 2; m++)
        wmma::store_matrix_sync(Yp + (size_t)(m*16)*N + n0 + warp*16, c[m],
                                N, wmma::mem_row_major);
}

// ---------------------------------------------------------------------------
// GRU gate math; sums KSPL partials; biases folded.
// ---------------------------------------------------------------------------
__global__ void k_gate(const float* __restrict__ giP, const float* __restrict__ ghP,
                       const float* __restrict__ bih, const float* __restrict__ bhh,
                       float* __restrict__ hf, __half* __restrict__ hH, __half* __restrict__ hL,
                       int writeY) {
    int i = blockIdx.x*blockDim.x + threadIdx.x;
    if (i >= Bdim*Hdim) return;
    int b = i / Hdim, j = i % Hdim;
    size_t o0 = (size_t)b*G3 + j;
    const size_t PS = (size_t)Bdim*G3;
    float gr = 0.f, gz = 0.f, gn = 0.f, hr = 0.f, hz = 0.f, hn = 0.f;
    #pragma unroll
    for (int s = 0; s < KSPL; s++) {
        gr += giP[s*PS + o0];
        gz += giP[s*PS + o0 + Hdim];
        gn += giP[s*PS + o0 + 2*Hdim];
        hr += ghP[s*PS + o0];
        hz += ghP[s*PS + o0 + Hdim];
        hn += ghP[s*PS + o0 + 2*Hdim];
    }
    float r = 1.f/(1.f + expf(-(gr + bih[j]        + hr + bhh[j])));
    float z = 1.f/(1.f + expf(-(gz + bih[Hdim+j]   + hz + bhh[Hdim+j])));
    float n = tanhf(gn + bih[2*Hdim+j] + r*(hn + bhh[2*Hdim+j]));
    float h = (1.f - z)*n + z*hf[i];
    hf[i] = h;
    split_write(h, hH + i, hL + i);
    if (writeY) {
        size_t yo = (size_t)b*2*Hdim + Hdim + j;
        split_write(h, d_yH + yo, d_yL + yo);
    }
}

// ---------------------------------------------------------------------------
// Attention per batch row; scores = fp32 h1 · Ck. grid (32), 256 threads.
// ---------------------------------------------------------------------------
__global__ void k_attn(const float* __restrict__ context) {
    int b = blockIdx.x;
    int tid = threadIdx.x;
    __shared__ float qs[Hdim];
    __shared__ float sc[Sdim];
    for (int j = tid; j < Hdim; j += 256) qs[j] = d_h1f[(size_t)b*Hdim + j];
    __syncthreads();
    int warp = tid >> 5, lane = tid & 31;
    for (int s = warp; s < Sdim; s += 8) {
        const float* cr = d_Ck + (size_t)(b*Sdim + s)*Hdim;
        float sum = 0.f;
        for (int j = lane; j < Hdim; j += 32) sum += qs[j]*cr[j];
        #pragma unroll
        for (int o = 16; o; o >>= 1) sum += __shfl_xor_sync(0xffffffffu, sum, o);
        if (!lane) sc[s] = sum;
    }
    __syncthreads();
    float m = -1e30f;
    for (int s = 0; s < Sdim; s++) m = fmaxf(m, sc[s]);
    float ssum = 0.f;
    for (int s = 0; s < Sdim; s++) ssum += expf(sc[s] - m);
    __syncthreads();
    if (tid < Sdim) sc[tid] = expf(sc[tid] - m) / ssum;
    __syncthreads();
    const float* cb = context + (size_t)b*Sdim*Hdim;
    for (int j = tid; j < Hdim; j += 256) {
        float acc = 0.f;
        #pragma unroll 8
        for (int s = 0; s < Sdim; s++) acc += sc[s]*cb[(size_t)s*Hdim + j];
        size_t yo = (size_t)b*2*Hdim + j;
        split_write(acc, d_yH + yo, d_yL + yo);
    }
}

// ---------------------------------------------------------------------------
// out partials = [c;h1] @ W_out^T, smem-staged pipeline. grid (16, KSPL).
// ---------------------------------------------------------------------------
__global__ void k_out() {
    __shared__ __align__(16) __half AsH[2][32*SLDA], AsL[2][32*SLDA];
    __shared__ __align__(16) __half BsH[2][64*SLDA], BsL[2][64*SLDA];
    int tid = threadIdx.x, warp = tid >> 5;
    int n0 = blockIdx.x*64;
    const int K = 2*Hdim;
    int kchunk = K / gridDim.y;
    int kbase = blockIdx.y * kchunk;

    wmma::fragment<wmma::accumulator,16,16,16,float> c[2];
    wmma::fill_fragment(c[0], 0.f);
    wmma::fill_fragment(c[1], 0.f);

    auto load = [&](int st, int k0) {
        {
            int r = tid >> 2, p = tid & 3;
            cp16(&AsH[st][r*SLDA + p*8], d_yH + (size_t)r*K + k0 + p*8);
            cp16(&AsL[st][r*SLDA + p*8], d_yL + (size_t)r*K + k0 + p*8);
        }
        #pragma unroll
        for (int rep = 0; rep < 2; rep++) {
            int ch = tid + rep*128;
            int r = ch >> 2, p = ch & 3;
            cp16(&BsH[st][r*SLDA + p*8], d_WoutH + (size_t)(n0+r)*K + k0 + p*8);
            cp16(&BsL[st][r*SLDA + p*8], d_WoutL + (size_t)(n0+r)*K + k0 + p*8);
        }
    };
    load(0, kbase);
    CP_COMMIT();
    const int nIter = kchunk/BK;
    for (int it = 0; it < nIter; ++it) {
        int cur = it & 1;
        if (it + 1 < nIter) { load(cur^1, kbase + (it+1)*BK); CP_COMMIT(); CP_WAIT(1); }
        else CP_WAIT(0);
        __syncthreads();
        #pragma unroll
        for (int ks = 0; ks < 2; ks++) {
            wmma::fragment<wmma::matrix_b,16,16,16,__half,wmma::col_major> bH, bL;
            wmma::load_matrix_sync(bH, &BsH[cur][(warp*16)*SLDA + ks*16], SLDA);
            wmma::load_matrix_sync(bL, &BsL[cur][(warp*16)*SLDA + ks*16], SLDA);
            #pragma unroll
            for (int m = 0; m < 2; m++) {
                wmma::fragment<wmma::matrix_a,16,16,16,__half,wmma::row_major> aH, aL;
                wmma::load_matrix_sync(aH, &AsH[cur][(m*16)*SLDA + ks*16], SLDA);
                wmma::load_matrix_sync(aL, &AsL[cur][(m*16)*SLDA + ks*16], SLDA);
                wmma::mma_sync(c[m], aH, bH, c[m]);
                wmma::mma_sync(c[m], aH, bL, c[m]);
                wmma::mma_sync(c[m], aL, bH, c[m]);
            }
        }
        __syncthreads();
    }
    float* Yp = d_oP + (size_t)blockIdx.y * Bdim * Hdim;
    #pragma unroll
    for (int m = 0; m < 2; m++)
        wmma::store_matrix_sync(Yp + (size_t)(m*16)*Hdim + n0 + warp*16, c[m],
                                Hdim, wmma::mem_row_major);
}

// ---------------------------------------------------------------------------
__global__ void k_outfin(int t) {
    int i = blockIdx.x*blockDim.x + threadIdx.x;
    if (i >= Bdim*Hdim) return;
    int b = i / Hdim, j = i % Hdim;
    const size_t PS = (size_t)Bdim*Hdim;
    float acc = 0.f;
    #pragma unroll
    for (int s = 0; s < KSPL; s++) acc += d_oP[s*PS + i];
    float v = tanhf(acc);
    d_outf[i] = v;
    d_OutAll[(size_t)t*Bdim*Hdim + i] = __float2half_rn(v);
    if (t + 1 < Tdim) {
        size_t xo = (size_t)((t+1)*Bdim + b)*KX + Edim + j;
        split_write(v, d_XH + xo, d_XL + xo);
    }
}

// ---------------------------------------------------------------------------
// Generator GEMM (unchanged). grid (500, 8), 256 threads.
// ---------------------------------------------------------------------------
#define GLDA 40
__global__ void k_gen(const float* __restrict__ bgen, float* __restrict__ logits) {
    __shared__ __align__(16) __half As[2][128*GLDA];
    __shared__ __align__(16) __half Bs[2][64*GLDA];
    __shared__ float Cs[64*68];
    int nb = blockIdx.x, mb = blockIdx.y;
    int n0 = nb*64, m0 = mb*128;
    int tid = threadIdx.x, warp = tid >> 5;
    int wm = warp >> 1, wn = warp & 1;
    const int K = Hdim;
    wmma::fragment<wmma::accumulator, 16,16,16, float> c[2][2];
    #pragma unroll
    for (int i = 0; i < 2; i++)
        #pragma unroll
        for (int j = 0; j < 2; j++)
            wmma::fill_fragment(c[i][j], 0.f);

    auto loadStage = [&](int stage, int kt) {
        int k0 = kt*32;
        #pragma unroll
        for (int rep = 0; rep < 2; rep++) {
            int ch = tid + rep*256;
            int row = ch >> 2, part = ch & 3;
            cp16(&As[stage][row*GLDA + part*8],
                 &d_OutAll[(size_t)(m0+row)*K + k0 + part*8]);
        }
        {
            int row = tid >> 2, part = tid & 3;
            cp16(&Bs[stage][row*GLDA + part*8],
                 &d_Wgen[(size_t)(n0+row)*K + k0 + part*8]);
        }
    };

    loadStage(0, 0);
    CP_COMMIT();
    const int nIter = K/32;
    for (int kt = 0; kt < nIter; ++kt) {
        int cur = kt & 1;
        if (kt + 1 < nIter) { loadStage(cur ^ 1, kt + 1); CP_COMMIT(); CP_WAIT(1); }
        else CP_WAIT(0);
        __syncthreads();
        #pragma unroll
        for (int s = 0; s < 32; s += 16) {
            wmma::fragment<wmma::matrix_a, 16,16,16, __half, wmma::row_major> a[2];
            wmma::fragment<wmma::matrix_b, 16,16,16, __half, wmma::col_major> bfr[2];
            #pragma unroll
            for (int i = 0; i < 2; i++)
                wmma::load_matrix_sync(a[i], &As[cur][(wm*32 + i*16)*GLDA + s], GLDA);
            #pragma unroll
            for (int j = 0; j < 2; j++)
                wmma::load_matrix_sync(bfr[j], &Bs[cur][(wn*32 + j*16)*GLDA + s], GLDA);
            #pragma unroll
            for (int i = 0; i < 2; i++)
                #pragma unroll
                for (int j = 0; j < 2; j++)
                    wmma::mma_sync(c[i][j], a[i], bfr[j], c[i][j]);
        }
        __syncthreads();
    }

    for (int hid = 0; hid < 2; ++hid) {
        if ((wm >> 1) == hid) {
            int wmL = wm & 1;
            #pragma unroll
            for (int i = 0; i < 2; i++)
                #pragma unroll
                for (int j = 0; j < 2; j++)
                    wmma::store_matrix_sync(&Cs[(wmL*32 + i*16)*68 + wn*32 + j*16],
                                            c[i][j], 68, wmma::mem_row_major);
        }
        __syncthreads();
        if (tid < 64) {
            int r = m0 + hid*64 + tid;
            float mx = -1e30f;
            for (int cc = 0; cc < 64; ++cc)
                mx = fmaxf(mx, Cs[tid*68 + cc] + bgen[n0 + cc]);
            float sm = 0.f;
            for (int cc = 0; cc < 64; ++cc)
                sm += expf(Cs[tid*68 + cc] + bgen[n0 + cc] - mx);
            d_partM[(size_t)r*NBLK + nb] = mx;
            d_partS[(size_t)r*NBLK + nb] = sm;
        }
        for (int e = tid; e < 64*64; e += 256) {
            int i = e >> 6, cc = e & 63;
            int r = m0 + hid*64 + i;
            logits[(size_t)r*Vdim + n0 + cc] = Cs[i*68 + cc] + bgen[n0 + cc];
        }
        __syncthreads();
    }
}

// ---------------------------------------------------------------------------
__global__ void k_combine() {
    int r = blockIdx.x, tid = threadIdx.x;
    float m = -1e30f, s = 0.f;
    for (int i = tid; i < NBLK; i += blockDim.x) {
        float mi = d_partM[(size_t)r*NBLK + i];
        float si = d_partS[(size_t)r*NBLK + i];
        float M = fmaxf(m, mi);
        s = s*expf(m - M) + si*expf(mi - M);
        m = M;
    }
    __shared__ float sm[128], ss[128];
    sm[tid] = m; ss[tid] = s;
    __syncthreads();
    for (int o = 64; o; o >>= 1) {
        if (tid < o) {
            float M = fmaxf(sm[tid], sm[tid+o]);
            ss[tid] = ss[tid]*expf(sm[tid] - M) + ss[tid+o]*expf(sm[tid+o] - M);
            sm[tid] = M;
        }
        __syncthreads();
    }
    if (!tid) d_lse[r] = sm[0] + logf(ss[0]);
}

__global__ void k_norm(float* __restrict__ logits) {
    int r = blockIdx.y;
    int i = blockIdx.x*blockDim.x + threadIdx.x;
    if (i < Vdim/4) {
        float4* p = (float4*)(logits + (size_t)r*Vdim);
        float l = d_lse[r];
        float4 v = p[i];
        v.x -= l; v.y -= l; v.z -= l; v.w -= l;
        p[i] = v;
    }
}

__global__ void k_final(float* __restrict__ tail) {
    int i = blockIdx.x*blockDim.x + threadIdx.x;
    const int BH = Bdim*Hdim;
    if (i < BH) {
        tail[i]        = d_h0f[i];
        tail[BH + i]   = d_h1f[i];
        tail[2*BH + i] = d_outf[i];
    }
}

// ---------------------------------------------------------------------------
extern "C" void kernel_launch(void* const* d_in, const int* in_sizes, int n_in,
                              void* d_out, int out_size) {
    (void)in_sizes; (void)n_in; (void)out_size;
    const int*   word_ids = (const int*)  d_in[0];
    const int*   spec_ids = (const int*)  d_in[1];
    const float* word_emb = (const float*)d_in[3];
    const float* spec_emb = (const float*)d_in[4];
    const float* wih0     = (const float*)d_in[5];
    const float* whh0     = (const float*)d_in[6];
    const float* bih0     = (const float*)d_in[7];
    const float* bhh0     = (const float*)d_in[8];
    const float* wih1     = (const float*)d_in[9];
    const float* whh1     = (const float*)d_in[10];
    const float* bih1     = (const float*)d_in[11];
    const float* bhh1     = (const float*)d_in[12];
    const float* Wa       = (const float*)d_in[13];
    const float* Wout     = (const float*)d_in[14];
    const float* Wgen     = (const float*)d_in[15];
    const float* bgen     = (const float*)d_in[16];
    const float* hidden   = (const float*)d_in[17];
    const float* pout     = (const float*)d_in[18];
    const float* context  = (const float*)d_in[19];
    float* outp = (float*)d_out;

    #define SYM(sym, ty, name) ty* name; { void* _p; cudaGetSymbolAddress(&_p, sym); name = (ty*)_p; }
    SYM(d_wih0H, __half, pwih0H)  SYM(d_wih0L, __half, pwih0L)
    SYM(d_whh0H, __half, pwhh0H)  SYM(d_whh0L, __half, pwhh0L)
    SYM(d_wih1H, __half, pwih1H)  SYM(d_wih1L, __half, pwih1L)
    SYM(d_whh1H, __half, pwhh1H)  SYM(d_whh1L, __half, pwhh1L)
    SYM(d_XH,    __half, pXH)     SYM(d_XL,    __half, pXL)
    SYM(d_h0H,   __half, ph0H)    SYM(d_h0L,   __half, ph0L)
    SYM(d_h1H,   __half, ph1H)    SYM(d_h1L,   __half, ph1L)
    SYM(d_h0f,   float,  ph0f)    SYM(d_h1f,   float,  ph1f)
    SYM(d_giP,   float,  pgiP)    SYM(d_ghP,   float,  pghP)
    #undef SYM

    k_cvt<<<4096, 256>>>(wih0, whh0, wih1, whh1, Wa, Wout, context, Wgen);
    k_embed<<<dim3(Tdim, Bdim), 256>>>(word_ids, spec_ids, word_emb, spec_emb);
    k_init<<<(Bdim*Hdim + 255)/256, 256>>>(hidden, pout);
    k_ck<<<dim3(16, 32), 128>>>();

    const int BH = Bdim*Hdim;
    for (int t = 0; t < Tdim; ++t) {
        const __half* XtH = pXH + (size_t)t*Bdim*KX;
        const __half* XtL = pXL + (size_t)t*Bdim*KX;
        k_gru_gemm<<<dim3(48,KSPL,2), 128>>>(XtH, XtL, KX, pwih0H, pwih0L, pgiP,
                                             ph0H, ph0L, Hdim, pwhh0H, pwhh0L, pghP, G3);
        k_gate<<<(BH + 255)/256, 256>>>(pgiP, pghP, bih0, bhh0, ph0f, ph0H, ph0L, 0);
        k_gru_gemm<<<dim3(48,KSPL,2), 128>>>(ph0H, ph0L, Hdim, pwih1H, pwih1L, pgiP,
                                             ph1H, ph1L, Hdim, pwhh1H, pwhh1L, pghP, G3);
        k_gate<<<(BH + 255)/256, 256>>>(pgiP, pghP, bih1, bhh1, ph1f, ph1H, ph1L, 1);
        k_attn<<<Bdim, 256>>>(context);
        k_out<<<dim3(16,KSPL), 128>>>();
        k_outfin<<<(BH + 255)/256, 256>>>(t);
    }

    k_gen<<<dim3(NBLK, MROWS/128), 256>>>(bgen, outp);
    k_combine<<<MROWS, 128>>>();
    k_norm<<<dim3(32, MROWS), 256>>>(outp);
    k_final<<<(BH + 255)/256, 256>>>(outp + (size_t)MROWS*Vdim);
}